// round 15
// baseline (speedup 1.0000x reference)
#include <cuda_runtime.h>

#define N_NODES 4096
#define F_IN 256
#define D_OUT 128
#define EPG (N_NODES * N_NODES / 2)   // 8388608
#define TOTAL_EDGES (2 * EPG)          // 16777216
#define NSEG (2 * N_NODES)             // 8192
#define PBLK 592                       // 148 SMs x 4 persistent blocks of 512

__device__ __align__(16) float g_ws[F_IN];
__device__ __align__(16) float g_wd[F_IN];
__device__ __align__(16) float g_as[NSEG];
__device__ __align__(16) float g_ad[NSEG];
__device__ __align__(16) float g_denom[NSEG];

// Fold W into attention vectors; also zero the denominators.
__global__ void k_prep(const float* __restrict__ W,
                       const float* __restrict__ att_src,
                       const float* __restrict__ att_dst) {
    int t = blockIdx.x * 256 + threadIdx.x;
    g_denom[t] = 0.0f;
    if (blockIdx.x == 0) {
        int f = threadIdx.x;
        float s = 0.f, d = 0.f;
        #pragma unroll 8
        for (int j = 0; j < D_OUT; ++j) {
            float w = W[f * D_OUT + j];
            s = fmaf(w, att_src[j], s);
            d = fmaf(w, att_dst[j], d);
        }
        g_ws[f] = s;
        g_wd[f] = d;
    }
}

// Per-node logits: one warp per node.
__global__ void k_node(const float* __restrict__ x1,
                       const float* __restrict__ x2) {
    int warp = (blockIdx.x * blockDim.x + threadIdx.x) >> 5;
    int lane = threadIdx.x & 31;
    const float* xrow = (warp < N_NODES) ? (x1 + (size_t)warp * F_IN)
                                         : (x2 + (size_t)(warp - N_NODES) * F_IN);
    const float4* X  = reinterpret_cast<const float4*>(xrow);
    const float4* WS = reinterpret_cast<const float4*>(g_ws);
    const float4* WD = reinterpret_cast<const float4*>(g_wd);
    float s = 0.f, d = 0.f;
    #pragma unroll
    for (int k = 0; k < 2; ++k) {
        float4 xv = X[lane + 32 * k];
        float4 ws = WS[lane + 32 * k];
        float4 wd = WD[lane + 32 * k];
        s = fmaf(xv.x, ws.x, fmaf(xv.y, ws.y, fmaf(xv.z, ws.z, fmaf(xv.w, ws.w, s))));
        d = fmaf(xv.x, wd.x, fmaf(xv.y, wd.y, fmaf(xv.z, wd.z, fmaf(xv.w, wd.w, d))));
    }
    #pragma unroll
    for (int off = 16; off > 0; off >>= 1) {
        s += __shfl_xor_sync(0xffffffffu, s, off);
        d += __shfl_xor_sync(0xffffffffu, d, off);
    }
    if (lane == 0) { g_as[warp] = s; g_ad[warp] = d; }
}

// Pass 1 (per graph): 512-thread persistent blocks; smem logit tables;
// denom accumulated in per-block smem ATOMS, flushed once.
__global__ void __launch_bounds__(512, 4)
k_pass1(const int* __restrict__ ei, int node_off) {
    __shared__ float s_as[N_NODES];
    __shared__ float s_ad[N_NODES];
    __shared__ float s_den[N_NODES];
    for (int t = threadIdx.x; t < N_NODES / 4; t += 512) {
        reinterpret_cast<float4*>(s_as)[t] =
            reinterpret_cast<const float4*>(g_as + node_off)[t];
        reinterpret_cast<float4*>(s_ad)[t] =
            reinterpret_cast<const float4*>(g_ad + node_off)[t];
        reinterpret_cast<float4*>(s_den)[t] = make_float4(0.f, 0.f, 0.f, 0.f);
    }
    __syncthreads();

    const int4* S = reinterpret_cast<const int4*>(ei);
    const int4* D = reinterpret_cast<const int4*>(ei + EPG);
    const int stride = PBLK * 512;
    for (int i = blockIdx.x * 512 + threadIdx.x; i < EPG / 4; i += stride) {
        int4 s4 = S[i];
        int4 d4 = D[i];
        float t0 = s_as[s4.x] + s_ad[d4.x];
        float t1 = s_as[s4.y] + s_ad[d4.y];
        float t2 = s_as[s4.z] + s_ad[d4.z];
        float t3 = s_as[s4.w] + s_ad[d4.w];
        atomicAdd(&s_den[d4.x], __expf(fmaxf(t0, 0.2f * t0)));
        atomicAdd(&s_den[d4.y], __expf(fmaxf(t1, 0.2f * t1)));
        atomicAdd(&s_den[d4.z], __expf(fmaxf(t2, 0.2f * t2)));
        atomicAdd(&s_den[d4.w], __expf(fmaxf(t3, 0.2f * t3)));
    }
    __syncthreads();
    for (int t = threadIdx.x; t < N_NODES; t += 512)
        atomicAdd(&g_denom[node_off + t], s_den[t]);
}

// Pass 2 (per graph): fused {ad, invden} float2 table (both dst-indexed),
// reciprocal computed at table-load; write alpha ONCE.
__global__ void __launch_bounds__(512, 4)
k_pass2(const int* __restrict__ ei, int node_off, float* __restrict__ out) {
    __shared__ float  s_as[N_NODES];
    __shared__ float2 s_di[N_NODES];       // {ad, invden}
    for (int t = threadIdx.x; t < N_NODES / 4; t += 512)
        reinterpret_cast<float4*>(s_as)[t] =
            reinterpret_cast<const float4*>(g_as + node_off)[t];
    for (int t = threadIdx.x; t < N_NODES; t += 512)
        s_di[t] = make_float2(g_ad[node_off + t],
                              __frcp_rn(g_denom[node_off + t]));
    __syncthreads();

    const int4* S = reinterpret_cast<const int4*>(ei);
    const int4* D = reinterpret_cast<const int4*>(ei + EPG);
    const int stride = PBLK * 512;
    for (int i = blockIdx.x * 512 + threadIdx.x; i < EPG / 4; i += stride) {
        int4 s4 = S[i];
        int4 d4 = D[i];
        float2 q0 = s_di[d4.x];
        float2 q1 = s_di[d4.y];
        float2 q2 = s_di[d4.z];
        float2 q3 = s_di[d4.w];
        float t0 = s_as[s4.x] + q0.x;
        float t1 = s_as[s4.y] + q1.x;
        float t2 = s_as[s4.z] + q2.x;
        float t3 = s_as[s4.w] + q3.x;
        float4 v;
        v.x = __expf(fmaxf(t0, 0.2f * t0)) * q0.y;
        v.y = __expf(fmaxf(t1, 0.2f * t1)) * q1.y;
        v.z = __expf(fmaxf(t2, 0.2f * t2)) * q2.y;
        v.w = __expf(fmaxf(t3, 0.2f * t3)) * q3.y;
        reinterpret_cast<float4*>(out)[i] = v;
    }
}

extern "C" void kernel_launch(void* const* d_in, const int* in_sizes, int n_in,
                              void* d_out, int out_size) {
    const float* x1  = (const float*)d_in[0];
    const float* x2  = (const float*)d_in[1];
    const int*   ei1 = (const int*)d_in[2];
    const int*   ei2 = (const int*)d_in[3];
    const float* W   = (const float*)d_in[4];
    const float* asv = (const float*)d_in[5];
    const float* adv = (const float*)d_in[6];
    float* out = (float*)d_out;

    k_prep<<<NSEG / 256, 256>>>(W, asv, adv);
    k_node<<<NSEG / 8, 256>>>(x1, x2);
    k_pass1<<<PBLK, 512>>>(ei1, 0);
    k_pass1<<<PBLK, 512>>>(ei2, N_NODES);
    k_pass2<<<PBLK, 512>>>(ei1, 0,       out);
    k_pass2<<<PBLK, 512>>>(ei2, N_NODES, out + EPG);
}

// round 16
// speedup vs baseline: 1.0125x; 1.0125x over previous
#include <cuda_runtime.h>

#define N_NODES 4096
#define F_IN 256
#define D_OUT 128
#define EPG (N_NODES * N_NODES / 2)   // 8388608
#define TOTAL_EDGES (2 * EPG)          // 16777216
#define NSEG (2 * N_NODES)             // 8192
#define PBLK 592                       // 148 SMs x 4 persistent blocks of 512

__device__ __align__(16) float g_ws[F_IN];
__device__ __align__(16) float g_wd[F_IN];
__device__ __align__(16) float g_as[NSEG];
__device__ __align__(16) float g_ad[NSEG];
__device__ __align__(16) float g_denom[NSEG];

// Fold W into attention vectors; also zero the denominators.
__global__ void k_prep(const float* __restrict__ W,
                       const float* __restrict__ att_src,
                       const float* __restrict__ att_dst) {
    int t = blockIdx.x * 256 + threadIdx.x;
    g_denom[t] = 0.0f;
    if (blockIdx.x == 0) {
        int f = threadIdx.x;
        float s = 0.f, d = 0.f;
        #pragma unroll 8
        for (int j = 0; j < D_OUT; ++j) {
            float w = W[f * D_OUT + j];
            s = fmaf(w, att_src[j], s);
            d = fmaf(w, att_dst[j], d);
        }
        g_ws[f] = s;
        g_wd[f] = d;
    }
}

// Per-node logits: one warp per node.
__global__ void k_node(const float* __restrict__ x1,
                       const float* __restrict__ x2) {
    int warp = (blockIdx.x * blockDim.x + threadIdx.x) >> 5;
    int lane = threadIdx.x & 31;
    const float* xrow = (warp < N_NODES) ? (x1 + (size_t)warp * F_IN)
                                         : (x2 + (size_t)(warp - N_NODES) * F_IN);
    const float4* X  = reinterpret_cast<const float4*>(xrow);
    const float4* WS = reinterpret_cast<const float4*>(g_ws);
    const float4* WD = reinterpret_cast<const float4*>(g_wd);
    float s = 0.f, d = 0.f;
    #pragma unroll
    for (int k = 0; k < 2; ++k) {
        float4 xv = X[lane + 32 * k];
        float4 ws = WS[lane + 32 * k];
        float4 wd = WD[lane + 32 * k];
        s = fmaf(xv.x, ws.x, fmaf(xv.y, ws.y, fmaf(xv.z, ws.z, fmaf(xv.w, ws.w, s))));
        d = fmaf(xv.x, wd.x, fmaf(xv.y, wd.y, fmaf(xv.z, wd.z, fmaf(xv.w, wd.w, d))));
    }
    #pragma unroll
    for (int off = 16; off > 0; off >>= 1) {
        s += __shfl_xor_sync(0xffffffffu, s, off);
        d += __shfl_xor_sync(0xffffffffu, d, off);
    }
    if (lane == 0) { g_as[warp] = s; g_ad[warp] = d; }
}

// Pass 1 (per graph): 512-thread persistent blocks; smem logit tables;
// denom accumulated in per-block smem ATOMS, flushed once.
__global__ void __launch_bounds__(512, 4)
k_pass1(const int* __restrict__ ei, int node_off) {
    __shared__ float s_as[N_NODES];
    __shared__ float s_ad[N_NODES];
    __shared__ float s_den[N_NODES];
    for (int t = threadIdx.x; t < N_NODES / 4; t += 512) {
        reinterpret_cast<float4*>(s_as)[t] =
            reinterpret_cast<const float4*>(g_as + node_off)[t];
        reinterpret_cast<float4*>(s_ad)[t] =
            reinterpret_cast<const float4*>(g_ad + node_off)[t];
        reinterpret_cast<float4*>(s_den)[t] = make_float4(0.f, 0.f, 0.f, 0.f);
    }
    __syncthreads();

    const int4* S = reinterpret_cast<const int4*>(ei);
    const int4* D = reinterpret_cast<const int4*>(ei + EPG);
    const int stride = PBLK * 512;
    for (int i = blockIdx.x * 512 + threadIdx.x; i < EPG / 4; i += stride) {
        int4 s4 = S[i];
        int4 d4 = D[i];
        float t0 = s_as[s4.x] + s_ad[d4.x];
        float t1 = s_as[s4.y] + s_ad[d4.y];
        float t2 = s_as[s4.z] + s_ad[d4.z];
        float t3 = s_as[s4.w] + s_ad[d4.w];
        atomicAdd(&s_den[d4.x], __expf(fmaxf(t0, 0.2f * t0)));
        atomicAdd(&s_den[d4.y], __expf(fmaxf(t1, 0.2f * t1)));
        atomicAdd(&s_den[d4.z], __expf(fmaxf(t2, 0.2f * t2)));
        atomicAdd(&s_den[d4.w], __expf(fmaxf(t3, 0.2f * t3)));
    }
    __syncthreads();
    for (int t = threadIdx.x; t < N_NODES; t += 512)
        atomicAdd(&g_denom[node_off + t], s_den[t]);
}

// Pass 2 (per graph): fused {ad, invden} float2 table (both dst-indexed),
// reciprocal computed at table-load; write alpha ONCE.
__global__ void __launch_bounds__(512, 4)
k_pass2(const int* __restrict__ ei, int node_off, float* __restrict__ out) {
    __shared__ float  s_as[N_NODES];
    __shared__ float2 s_di[N_NODES];       // {ad, invden}
    for (int t = threadIdx.x; t < N_NODES / 4; t += 512)
        reinterpret_cast<float4*>(s_as)[t] =
            reinterpret_cast<const float4*>(g_as + node_off)[t];
    for (int t = threadIdx.x; t < N_NODES; t += 512)
        s_di[t] = make_float2(g_ad[node_off + t],
                              __frcp_rn(g_denom[node_off + t]));
    __syncthreads();

    const int4* S = reinterpret_cast<const int4*>(ei);
    const int4* D = reinterpret_cast<const int4*>(ei + EPG);
    const int stride = PBLK * 512;
    for (int i = blockIdx.x * 512 + threadIdx.x; i < EPG / 4; i += stride) {
        int4 s4 = S[i];
        int4 d4 = D[i];
        float2 q0 = s_di[d4.x];
        float2 q1 = s_di[d4.y];
        float2 q2 = s_di[d4.z];
        float2 q3 = s_di[d4.w];
        float t0 = s_as[s4.x] + q0.x;
        float t1 = s_as[s4.y] + q1.x;
        float t2 = s_as[s4.z] + q2.x;
        float t3 = s_as[s4.w] + q3.x;
        float4 v;
        v.x = __expf(fmaxf(t0, 0.2f * t0)) * q0.y;
        v.y = __expf(fmaxf(t1, 0.2f * t1)) * q1.y;
        v.z = __expf(fmaxf(t2, 0.2f * t2)) * q2.y;
        v.w = __expf(fmaxf(t3, 0.2f * t3)) * q3.y;
        reinterpret_cast<float4*>(out)[i] = v;
    }
}

extern "C" void kernel_launch(void* const* d_in, const int* in_sizes, int n_in,
                              void* d_out, int out_size) {
    const float* x1  = (const float*)d_in[0];
    const float* x2  = (const float*)d_in[1];
    const int*   ei1 = (const int*)d_in[2];
    const int*   ei2 = (const int*)d_in[3];
    const float* W   = (const float*)d_in[4];
    const float* asv = (const float*)d_in[5];
    const float* adv = (const float*)d_in[6];
    float* out = (float*)d_out;

    k_prep<<<NSEG / 256, 256>>>(W, asv, adv);
    k_node<<<NSEG / 8, 256>>>(x1, x2);
    k_pass1<<<PBLK, 512>>>(ei1, 0);
    k_pass1<<<PBLK, 512>>>(ei2, N_NODES);
    k_pass2<<<PBLK, 512>>>(ei1, 0,       out);
    k_pass2<<<PBLK, 512>>>(ei2, N_NODES, out + EPG);
}